// round 16
// baseline (speedup 1.0000x reference)
#include <cuda_runtime.h>
#include <cuda_fp16.h>
#include <cstdint>

#define BATCH 32
#define TLEN  1024
#define HID   128
#define LD_H  144              // halves per padded row (288 B) — gmem AND smem
#define NT    512
#define NCTA  144
#define LOG2E 1.4426950408889634f

#define TILE_B (128 * LD_H * 2)        // 36864 B
#define SM_Q0  0
#define SM_Q1  TILE_B
#define SM_K   (2 * TILE_B)            // 3 slots
#define SM_Y   (5 * TILE_B)            // 5 slots * 512 B (slot 4 = next-job y)
#define SM_TOT (SM_Y + 5 * 512)        // 2 * 2048 B
#define SMEM_BYTES (SM_TOT + 4096)

__device__ __half    g_xn[(size_t)BATCH * TLEN * LD_H];  // fp16, kp-interleaved frags
__device__ float     g_nl2[BATCH * TLEN];                // -lambda * log2(e)
__device__ unsigned  g_flags[256];                       // per-tile monotonic counters
__device__ unsigned  g_all;                              // CTAs-published counter
__device__ unsigned  g_epoch[NCTA];                      // per-CTA invocation counter

__device__ __forceinline__ float ex2f(float x) {
    float y; asm("ex2.approx.ftz.f32 %0, %1;" : "=f"(y) : "f"(x)); return y;
}
__device__ __forceinline__ void mma_f16(float* c, uint32_t a0, uint32_t a1,
                                        uint32_t a2, uint32_t a3,
                                        uint32_t b0, uint32_t b1) {
    asm volatile(
        "mma.sync.aligned.m16n8k16.row.col.f32.f16.f16.f32 "
        "{%0,%1,%2,%3}, {%4,%5,%6,%7}, {%8,%9}, {%0,%1,%2,%3};"
        : "+f"(c[0]), "+f"(c[1]), "+f"(c[2]), "+f"(c[3])
        : "r"(a0), "r"(a1), "r"(a2), "r"(a3), "r"(b0), "r"(b1));
}
__device__ __forceinline__ void cp16(uint32_t dst, const void* src) {      // via L1
    asm volatile("cp.async.ca.shared.global [%0], [%1], 16;" :: "r"(dst), "l"(src));
}
__device__ __forceinline__ void cg16(uint32_t dst, const void* src) {      // L2 only
    asm volatile("cp.async.cg.shared.global [%0], [%1], 16;" :: "r"(dst), "l"(src));
}
__device__ __forceinline__ void cp_commit() {
    asm volatile("cp.async.commit_group;" ::: "memory");
}
__device__ __forceinline__ void cp_wait(bool allow_one) {
    if (allow_one) asm volatile("cp.async.wait_group 1;" ::: "memory");
    else           asm volatile("cp.async.wait_group 0;" ::: "memory");
}

// copy one 128-row tile (linear, 2304 x 16B)
__device__ __forceinline__ void tile_copy(uint32_t dst, const char* src, int tid) {
    #pragma unroll
    for (int i = 0; i < 4; ++i) {
        const int c = tid + i * 512;
        cg16(dst + c * 16, src + c * 16);
    }
    if (tid < 256) {
        const int c = tid + 2048;
        cg16(dst + c * 16, src + c * 16);
    }
}

// ---- one 128x128 key block: GEMM + fragment scan ----
template<bool DIAG>
__device__ __forceinline__ void process_block(
    const __half* q_h, const __half* b_h, const float* yblk, float* totbuf,
    const float* nl2r, const int* rown, float* carry, float* Sacc, float* Yacc,
    int mrow0, int cb, int cw, int g, int tg, int tgbase, bool allow_one)
{
    const unsigned FULL = 0xffffffffu;
    const bool live = !DIAG || (cb <= mrow0);

    float acc[2][4][4];
    #pragma unroll
    for (int mt = 0; mt < 2; mt++)
        #pragma unroll
        for (int nt = 0; nt < 4; nt++)
            #pragma unroll
            for (int j = 0; j < 4; j++) acc[mt][nt][j] = 0.f;

    if (live) {
        #pragma unroll
        for (int kp = 0; kp < 4; ++kp) {
            const int aoff = tgbase + kp * 8;
            uint4 a0 = *(const uint4*)&q_h[(mrow0 +      g) * LD_H + aoff];
            uint4 a1 = *(const uint4*)&q_h[(mrow0 +  8 + g) * LD_H + aoff];
            uint4 a2 = *(const uint4*)&q_h[(mrow0 + 16 + g) * LD_H + aoff];
            uint4 a3 = *(const uint4*)&q_h[(mrow0 + 24 + g) * LD_H + aoff];
            #pragma unroll
            for (int nt = 0; nt < 4; ++nt) {
                uint4 b = *(const uint4*)&b_h[(cb + nt * 8 + g) * LD_H + aoff];
                mma_f16(acc[0][nt], a0.x, a1.x, a0.y, a1.y, b.x, b.y);
                mma_f16(acc[1][nt], a2.x, a3.x, a2.y, a3.y, b.x, b.y);
                mma_f16(acc[0][nt], a0.z, a1.z, a0.w, a1.w, b.z, b.w);
                mma_f16(acc[1][nt], a2.z, a3.z, a2.w, a3.w, b.z, b.w);
            }
        }
    }

    // mask + (x+1)/2
    const int col0 = cb + 2 * tg;
    #pragma unroll
    for (int i = 0; i < 4; ++i) {
        const int mt = i >> 1, c0i = (i & 1) * 2;
        #pragma unroll
        for (int nt = 0; nt < 4; nt++) {
            float va = fmaf(acc[mt][nt][c0i],     0.5f, 0.5f);
            float vb = fmaf(acc[mt][nt][c0i + 1], 0.5f, 0.5f);
            if (DIAG) {
                va = (col0 + nt * 8     < rown[i]) ? va : 0.f;
                vb = (col0 + nt * 8 + 1 < rown[i]) ? vb : 0.f;
            }
            acc[mt][nt][c0i]     = va;
            acc[mt][nt][c0i + 1] = vb;
        }
    }

    // per (row,frag): suffix over the 4 lanes of the group
    float sarr[4][4], ft[4][4];
    #pragma unroll
    for (int i = 0; i < 4; ++i) {
        const int mt = i >> 1, c0i = (i & 1) * 2;
        #pragma unroll
        for (int nt = 0; nt < 4; nt++) {
            float s = acc[mt][nt][c0i] + acc[mt][nt][c0i + 1];
            float u = __shfl_down_sync(FULL, s, 1);
            s += (tg < 3) ? u : 0.f;
            u = __shfl_down_sync(FULL, s, 2);
            s += (tg < 2) ? u : 0.f;
            sarr[i][nt] = s;
            ft[i][nt] = __shfl_sync(FULL, s, (threadIdx.x & 31) & ~3);
        }
    }

    if (tg == 0) {
        #pragma unroll
        for (int i = 0; i < 4; ++i)
            totbuf[cw * 128 + rown[i]] = ft[i][0] + ft[i][1] + ft[i][2] + ft[i][3];
    }

    // y pairs: published a block earlier — safe to read before this barrier
    float2 yp[4];
    #pragma unroll
    for (int nt = 0; nt < 4; nt++)
        yp[nt] = *(const float2*)&yblk[cb + nt * 8 + 2 * tg];

    cp_wait(allow_one);
    __syncthreads();        // totals + previously-issued cp groups visible

    #pragma unroll
    for (int i = 0; i < 4; ++i) {
        const int r = rown[i];
        const float c0t = totbuf[r],       c1t = totbuf[128 + r],
                    c2t = totbuf[256 + r], c3t = totbuf[384 + r];
        float base = carry[i];
        if (cw == 0)      base += c1t + c2t + c3t;
        else if (cw == 1) base += c2t + c3t;
        else if (cw == 2) base += c3t;
        carry[i] += c0t + c1t + c2t + c3t;

        if (live) {
            const int mt = i >> 1, c0i = (i & 1) * 2;
            float fsuf = 0.f;
            #pragma unroll
            for (int nt = 3; nt >= 0; --nt) {
                const float va = acc[mt][nt][c0i];
                const float vb = acc[mt][nt][c0i + 1];
                const float sa = base + fsuf + sarr[i][nt];
                const float wa = va * ex2f(nl2r[i] * sa);
                const float wb = vb * ex2f(nl2r[i] * (sa - va));
                Sacc[i] += wa + wb;
                Yacc[i] += yp[nt].x * wa + yp[nt].y * wb;
                fsuf += ft[i][nt];
            }
        }
    }
}

// ---- fused kernel: distributed prep (flagged) overlapped with main ----
__global__ __launch_bounds__(NT, 1)
void ema_kernel(const float* __restrict__ y,
                const int*   __restrict__ seq,
                const float* __restrict__ embd,
                const float* __restrict__ lam_w,
                const float* __restrict__ lam_b,
                float*       __restrict__ out)
{
    extern __shared__ char smem[];
    __half* q_b[2] = { (__half*)(smem + SM_Q0), (__half*)(smem + SM_Q1) };
    float*  ys   = (float*)(smem + SM_Y);
    float*  tot  = (float*)(smem + SM_TOT);
    __shared__ unsigned s_ep;

    const uint32_t q_sa[2] = { (uint32_t)__cvta_generic_to_shared(smem + SM_Q0),
                               (uint32_t)__cvta_generic_to_shared(smem + SM_Q1) };
    const uint32_t k_sa0 = (uint32_t)__cvta_generic_to_shared(smem + SM_K);
    const uint32_t y_sa  = (uint32_t)__cvta_generic_to_shared(smem + SM_Y);

    const int tid  = threadIdx.x;
    const int lane = tid & 31;
    const int wid  = tid >> 5;
    const unsigned FULL = 0xffffffffu;
    const int bid  = blockIdx.x;

    // kp-interleave constants (lane-only)
    const int u_      = (lane >> 1) & 7;
    const int tg      = lane & 3;
    const int ptg     = u_ & 3;
    const int hi2     = (u_ >> 2) * 2;
    const int ptgbase = ptg * 32 + (ptg >> 1) * 8;   // prep store base {0,32,72,104}
    const int tgbase  = tg * 32 + (tg >> 1) * 8;     // GEMM load base

    // ---- epoch (replay-safe monotonic) ----
    if (tid == 0) s_ep = atomicAdd(&g_epoch[bid], 1u);
    __syncthreads();
    const unsigned ftarget = s_ep + 1u;
    const unsigned atarget = (s_ep + 1u) * NCTA;
    bool all_ready = false;

    // ---- Phase 1: prep this CTA's tiles (ILP'd), publish flags ----
    {
        const float l0 = lam_w[lane],      l1 = lam_w[lane + 32],
                    l2 = lam_w[lane + 64], l3 = lam_w[lane + 96];
        const float lb = lam_b[0];

        int tb[2], tq[2], ntl;
        if (bid < 32)       { tb[0] = bid;       tq[0] = 7; ntl = 1; }
        else if (bid < 64)  { tb[0] = bid - 32;  tq[0] = 6; ntl = 2; }
        else if (bid < 96)  { tb[0] = bid - 64;  tq[0] = 5; ntl = 2; }
        else if (bid < 128) { tb[0] = bid - 96;  tq[0] = 4; ntl = 2; }
        else                { tb[0] = 2 * (bid - 128); tq[0] = 3; ntl = 2; }
        if (ntl == 2) {
            if (bid < 48)       { tb[1] = 2 * (bid - 32) + 1; tq[1] = 3; }
            else if (bid < 80)  { tb[1] = bid - 48;  tq[1] = 2; }
            else if (bid < 112) { tb[1] = bid - 80;  tq[1] = 1; }
            else                { tb[1] = bid - 112; tq[1] = 0; }
        }

        for (int t = 0; t < ntl; ++t) {
            const int T  = tb[t] * 8 + tq[t];
            const int r0 = tb[t] * TLEN + tq[t] * 128 + wid * 8;
            int e[8];
            #pragma unroll
            for (int i = 0; i < 8; ++i) e[i] = seq[r0 + i];
            float v[8][4];
            #pragma unroll
            for (int i = 0; i < 8; ++i) {
                const float* w = embd + (size_t)e[i] * HID;
                v[i][0] = w[lane];      v[i][1] = w[lane + 32];
                v[i][2] = w[lane + 64]; v[i][3] = w[lane + 96];
            }
            #pragma unroll
            for (int i = 0; i < 8; ++i) {
                float ss = v[i][0]*v[i][0] + v[i][1]*v[i][1]
                         + v[i][2]*v[i][2] + v[i][3]*v[i][3];
                float dl = v[i][0]*l0 + v[i][1]*l1 + v[i][2]*l2 + v[i][3]*l3;
                #pragma unroll
                for (int off = 16; off; off >>= 1) {
                    ss += __shfl_xor_sync(FULL, ss, off);
                    dl += __shfl_xor_sync(FULL, dl, off);
                }
                const float inv = rsqrtf(ss);
                __half* dst = g_xn + (size_t)(r0 + i) * LD_H;
                #pragma unroll
                for (int q = 0; q < 4; ++q) {
                    const __half h = __float2half_rn(v[i][q] * inv);
                    uint32_t mine = (uint32_t)__half_as_ushort(h);
                    uint32_t part = __shfl_down_sync(FULL, mine, 1);
                    if (!(lane & 1)) {
                        const int ks  = (lane >> 4) + 2 * q;
                        const int pos = ptgbase + ks * 4 + hi2;
                        *(uint32_t*)(dst + pos) = (part << 16) | mine;
                    }
                }
                if (lane == 0) g_nl2[r0 + i] = -__expf(dl + lb) * LOG2E;
            }
            __syncthreads();
            if (tid == 0) { __threadfence(); atomicAdd(&g_flags[T], 1u); }
        }
        if (tid == 0) { __threadfence(); atomicAdd(&g_all, 1u); }
    }

    // per-tile readiness wait (fast path: one g_all check, then free)
    auto wait_tile = [&](int T) {
        if (!all_ready) {
            if (*((volatile unsigned*)&g_all) >= atarget) {
                all_ready = true;
            } else {
                while (*((volatile unsigned*)&g_flags[T]) < ftarget) __nanosleep(64);
            }
            __threadfence();
        }
    };

    // ---- Phase 2: main (R15 structure) ----
    const int g  = lane >> 2;
    const int mrow0 = (wid >> 2) * 32;
    const int cw    = wid & 3;
    const int cb    = cw * 32;

    int jb[2], jq[2], njobs;
    if (bid < 32)       { jb[0] = bid;            jq[0] = 7; njobs = 1; }
    else if (bid < 64)  { jb[0] = bid - 32;  jq[0] = 6; jb[1] = jb[0]; jq[1] = 0; njobs = 2; }
    else if (bid < 96)  { jb[0] = bid - 64;  jq[0] = 5; jb[1] = jb[0]; jq[1] = 1; njobs = 2; }
    else if (bid < 128) { jb[0] = bid - 96;  jq[0] = 4; jb[1] = jb[0]; jq[1] = 2; njobs = 2; }
    else { jb[0] = 2 * (bid - 128); jq[0] = 3; jb[1] = jb[0] + 1; jq[1] = 3; njobs = 2; }

    int rown[4];
    #pragma unroll
    for (int i = 0; i < 4; ++i) rown[i] = mrow0 + 8 * i + g;

    for (int j = 0; j < njobs; ++j) {
        const int batch = jb[j];
        const int qi    = jq[j];
        const int t0    = qi * 128;

        const __half* xbase = g_xn + (size_t)batch * TLEN * LD_H;
        const float*  ybase = y + batch * TLEN;
        const __half* q_h   = q_b[j];

        if (j == 0) {
            wait_tile(batch * 8 + qi);
            tile_copy(q_sa[0], (const char*)(xbase + (size_t)t0 * LD_H), tid);
            if (tid < 32) cp16(y_sa + (qi & 3) * 512 + tid * 16,
                               ybase + qi * 128 + tid * 4);
            cp_commit();
        }
        bool havek = (qi >= 1);
        if (havek) {
            wait_tile(batch * 8 + qi - 1);
            tile_copy(k_sa0 + ((qi - 1) % 3) * TILE_B,
                      (const char*)(xbase + (size_t)(qi - 1) * 128 * LD_H), tid);
            if (tid < 32) cp16(y_sa + ((qi - 1) & 3) * 512 + tid * 16,
                               ybase + (qi - 1) * 128 + tid * 4);
            cp_commit();
        }
        cp_wait(havek);     // Q group done; K(qi-1) may stay in flight
        __syncthreads();

        float nl2r[4];
        #pragma unroll
        for (int i = 0; i < 4; ++i)
            nl2r[i] = g_nl2[batch * TLEN + t0 + rown[i]];

        float carry[4] = {0.f, 0.f, 0.f, 0.f};
        float Sacc[4]  = {0.f, 0.f, 0.f, 0.f};
        float Yacc[4]  = {0.f, 0.f, 0.f, 0.f};

        for (int it = 0; it <= qi; ++it) {
            const int kb = qi - it;

            bool issued = false;
            if (kb - 2 >= 0) {
                wait_tile(batch * 8 + kb - 2);
                tile_copy(k_sa0 + ((kb - 2) % 3) * TILE_B,
                          (const char*)(xbase + (size_t)(kb - 2) * 128 * LD_H), tid);
                if (tid < 32) cp16(y_sa + ((kb - 2) & 3) * 512 + tid * 16,
                                   ybase + (kb - 2) * 128 + tid * 4);
                cp_commit();
                issued = true;
            } else if (it == qi && j == 0 && njobs == 2) {
                wait_tile(jb[1] * 8 + jq[1]);
                const __half* nxbase = g_xn + (size_t)jb[1] * TLEN * LD_H;
                tile_copy(q_sa[1], (const char*)(nxbase + (size_t)jq[1] * 128 * LD_H), tid);
                if (tid < 32) cp16(y_sa + 4 * 512 + tid * 16,
                                   y + jb[1] * TLEN + jq[1] * 128 + tid * 4);
                cp_commit();
                issued = true;
            }

            float* totbuf = tot + (it & 1) * 512;
            const float* yblk = (j > 0 && it == 0) ? (ys + 4 * 128)
                                                   : (ys + (kb & 3) * 128);
            if (it == 0) {
                process_block<true>(q_h, q_h, yblk, totbuf, nl2r, rown,
                                    carry, Sacc, Yacc, mrow0, cb, cw, g, tg,
                                    tgbase, issued);
            } else {
                const __half* bsrc = (const __half*)(smem + SM_K + (kb % 3) * TILE_B);
                process_block<false>(q_h, bsrc, yblk, totbuf, nl2r, rown,
                                     carry, Sacc, Yacc, mrow0, cb, cw, g, tg,
                                     tgbase, issued);
            }
        }

        // ---- epilogue ----
        __syncthreads();
        #pragma unroll
        for (int i = 0; i < 4; ++i) {
            float s = Sacc[i], yv = Yacc[i];
            s  += __shfl_xor_sync(FULL, s, 1);  s  += __shfl_xor_sync(FULL, s, 2);
            yv += __shfl_xor_sync(FULL, yv, 1); yv += __shfl_xor_sync(FULL, yv, 2);
            if (tg == 0) {
                tot[cw * 128 + rown[i]]       = s;
                tot[512 + cw * 128 + rown[i]] = yv;
            }
        }
        __syncthreads();
        if (cw == 0) {
            #pragma unroll
            for (int i = 0; i < 4; ++i) {
                const int r = rown[i];
                float S = tot[r] + tot[128 + r] + tot[256 + r] + tot[384 + r];
                float Y = tot[512 + r] + tot[640 + r] + tot[768 + r] + tot[896 + r];
                float o = Y / (S + 1e-6f);
                o = fminf(fmaxf(o, 0.01f), 0.99f);
                out[batch * TLEN + t0 + r] = o;
            }
        }
    }
}

extern "C" void kernel_launch(void* const* d_in, const int* in_sizes, int n_in,
                              void* d_out, int out_size)
{
    const float* y    = (const float*)d_in[0];
    const int*   seq  = (const int*)  d_in[1];
    const float* embd = (const float*)d_in[2];
    const float* lw   = (const float*)d_in[3];
    const float* lb   = (const float*)d_in[4];
    float* out = (float*)d_out;

    cudaFuncSetAttribute(ema_kernel,
                         cudaFuncAttributeMaxDynamicSharedMemorySize, SMEM_BYTES);

    ema_kernel<<<NCTA, NT, SMEM_BYTES>>>(y, seq, embd, lw, lb, out);
}

// round 17
// speedup vs baseline: 1.1080x; 1.1080x over previous
#include <cuda_runtime.h>
#include <cuda_fp16.h>
#include <cstdint>

#define BATCH 32
#define TLEN  1024
#define HID   128
#define LD_H  144              // halves per padded row (288 B) — gmem AND smem
#define NT    512
#define LOG2E 1.4426950408889634f

#define TILE_B (128 * LD_H * 2)        // 36864 B
#define SM_Q   0
#define SM_K0  TILE_B
#define SM_K1  (2 * TILE_B)
#define SM_Y   (3 * TILE_B)            // 2*128 floats
#define SM_TOT (SM_Y + 1024)           // 2*512 floats
#define SMEM_BYTES (SM_TOT + 4096)

__device__ __half g_xn[(size_t)BATCH * TLEN * LD_H];  // fp16, kp-interleaved frags
__device__ float  g_nl2[BATCH * TLEN];                // -lambda * log2(e)

__device__ __forceinline__ float ex2f(float x) {
    float y; asm("ex2.approx.ftz.f32 %0, %1;" : "=f"(y) : "f"(x)); return y;
}
__device__ __forceinline__ void mma_f16(float* c, uint32_t a0, uint32_t a1,
                                        uint32_t a2, uint32_t a3,
                                        uint32_t b0, uint32_t b1) {
    asm volatile(
        "mma.sync.aligned.m16n8k16.row.col.f32.f16.f16.f32 "
        "{%0,%1,%2,%3}, {%4,%5,%6,%7}, {%8,%9}, {%0,%1,%2,%3};"
        : "+f"(c[0]), "+f"(c[1]), "+f"(c[2]), "+f"(c[3])
        : "r"(a0), "r"(a1), "r"(a2), "r"(a3), "r"(b0), "r"(b1));
}
__device__ __forceinline__ void cp16(uint32_t dst, const void* src) {      // via L1
    asm volatile("cp.async.ca.shared.global [%0], [%1], 16;" :: "r"(dst), "l"(src));
}
__device__ __forceinline__ void cg16(uint32_t dst, const void* src) {      // L2 only
    asm volatile("cp.async.cg.shared.global [%0], [%1], 16;" :: "r"(dst), "l"(src));
}
__device__ __forceinline__ void cp_wait_all() {
    asm volatile("cp.async.wait_all;" ::: "memory");
}

// ---- Pass 1: normalize tokens; 2 rows per warp for gather MLP ----
__global__ __launch_bounds__(256)
void prep_kernel(const int* __restrict__ seq,
                 const float* __restrict__ embd,
                 const float* __restrict__ lam_w,
                 const float* __restrict__ lam_b)
{
    const int lane = threadIdx.x & 31;
    const int wid  = threadIdx.x >> 5;
    const int row0 = blockIdx.x * 16 + wid * 2;
    const unsigned FULL = 0xffffffffu;

    const int e0 = seq[row0];
    const int e1 = seq[row0 + 1];
    const float* w0 = embd + (size_t)e0 * HID;
    const float* w1 = embd + (size_t)e1 * HID;
    const float l0 = lam_w[lane],      l1 = lam_w[lane + 32],
                l2 = lam_w[lane + 64], l3 = lam_w[lane + 96];

    float a[4], b[4];
    a[0] = w0[lane]; a[1] = w0[lane+32]; a[2] = w0[lane+64]; a[3] = w0[lane+96];
    b[0] = w1[lane]; b[1] = w1[lane+32]; b[2] = w1[lane+64]; b[3] = w1[lane+96];

    float ss0 = a[0]*a[0] + a[1]*a[1] + a[2]*a[2] + a[3]*a[3];
    float dl0 = a[0]*l0 + a[1]*l1 + a[2]*l2 + a[3]*l3;
    float ss1 = b[0]*b[0] + b[1]*b[1] + b[2]*b[2] + b[3]*b[3];
    float dl1 = b[0]*l0 + b[1]*l1 + b[2]*l2 + b[3]*l3;
    #pragma unroll
    for (int off = 16; off; off >>= 1) {
        ss0 += __shfl_xor_sync(FULL, ss0, off);
        dl0 += __shfl_xor_sync(FULL, dl0, off);
        ss1 += __shfl_xor_sync(FULL, ss1, off);
        dl1 += __shfl_xor_sync(FULL, dl1, off);
    }
    const float inv0 = rsqrtf(ss0);
    const float inv1 = rsqrtf(ss1);

    const int u      = (lane >> 1) & 7;
    const int tg     = u & 3;
    const int hi2    = (u >> 2) * 2;
    const int tgbase = tg * 32 + (tg >> 1) * 8;    // {0,32,72,104}

    __half* d0 = g_xn + (size_t)row0 * LD_H;
    __half* d1 = d0 + LD_H;
    #pragma unroll
    for (int q = 0; q < 4; ++q) {
        const __half h0 = __float2half_rn(a[q] * inv0);
        const __half h1 = __float2half_rn(b[q] * inv1);
        uint32_t m0 = (uint32_t)__half_as_ushort(h0);
        uint32_t m1 = (uint32_t)__half_as_ushort(h1);
        uint32_t p0 = __shfl_down_sync(FULL, m0, 1);
        uint32_t p1 = __shfl_down_sync(FULL, m1, 1);
        if (!(lane & 1)) {
            const int ks  = (lane >> 4) + 2 * q;
            const int pos = tgbase + ks * 4 + hi2;
            *(uint32_t*)(d0 + pos) = (p0 << 16) | m0;
            *(uint32_t*)(d1 + pos) = (p1 << 16) | m1;
        }
    }
    if (lane == 0) {
        const float lb = lam_b[0];
        g_nl2[row0]     = -__expf(dl0 + lb) * LOG2E;
        g_nl2[row0 + 1] = -__expf(dl1 + lb) * LOG2E;
    }
}

// ---- one 128x128 key block: GEMM + fragment scan (single sync inside) ----
template<bool DIAG>
__device__ __forceinline__ void process_block(
    const __half* q_h, const __half* b_h, const float* yblk, float* totbuf,
    const float* nl2r, const int* rown, float* carry, float* Sacc, float* Yacc,
    int mrow0, int cb, int cw, int g, int tg, int tgbase)
{
    const unsigned FULL = 0xffffffffu;
    const bool live = !DIAG || (cb <= mrow0);   // fully-masked diag fragments skipped

    float acc[2][4][4];
    #pragma unroll
    for (int mt = 0; mt < 2; mt++)
        #pragma unroll
        for (int nt = 0; nt < 4; nt++)
            #pragma unroll
            for (int j = 0; j < 4; j++) acc[mt][nt][j] = 0.f;

    if (live) {
        #pragma unroll
        for (int kp = 0; kp < 4; ++kp) {        // two k-steps per iteration
            const int aoff = tgbase + kp * 8;   // halves
            uint4 a0 = *(const uint4*)&q_h[(mrow0 +      g) * LD_H + aoff];
            uint4 a1 = *(const uint4*)&q_h[(mrow0 +  8 + g) * LD_H + aoff];
            uint4 a2 = *(const uint4*)&q_h[(mrow0 + 16 + g) * LD_H + aoff];
            uint4 a3 = *(const uint4*)&q_h[(mrow0 + 24 + g) * LD_H + aoff];
            #pragma unroll
            for (int nt = 0; nt < 4; ++nt) {
                uint4 b = *(const uint4*)&b_h[(cb + nt * 8 + g) * LD_H + aoff];
                mma_f16(acc[0][nt], a0.x, a1.x, a0.y, a1.y, b.x, b.y);   // ks = 2kp
                mma_f16(acc[1][nt], a2.x, a3.x, a2.y, a3.y, b.x, b.y);
                mma_f16(acc[0][nt], a0.z, a1.z, a0.w, a1.w, b.z, b.w);   // ks = 2kp+1
                mma_f16(acc[1][nt], a2.z, a3.z, a2.w, a3.w, b.z, b.w);
            }
        }
    }

    // mask + (x+1)/2
    const int col0 = cb + 2 * tg;
    #pragma unroll
    for (int i = 0; i < 4; ++i) {
        const int mt = i >> 1, c0i = (i & 1) * 2;
        #pragma unroll
        for (int nt = 0; nt < 4; nt++) {
            float va = fmaf(acc[mt][nt][c0i],     0.5f, 0.5f);
            float vb = fmaf(acc[mt][nt][c0i + 1], 0.5f, 0.5f);
            if (DIAG) {
                va = (col0 + nt * 8     < rown[i]) ? va : 0.f;
                vb = (col0 + nt * 8 + 1 < rown[i]) ? vb : 0.f;
            }
            acc[mt][nt][c0i]     = va;
            acc[mt][nt][c0i + 1] = vb;
        }
    }

    // per (row,frag): suffix over the 4 lanes of the group
    float sarr[4][4], ft[4][4];
    #pragma unroll
    for (int i = 0; i < 4; ++i) {
        const int mt = i >> 1, c0i = (i & 1) * 2;
        #pragma unroll
        for (int nt = 0; nt < 4; nt++) {
            float s = acc[mt][nt][c0i] + acc[mt][nt][c0i + 1];
            float u = __shfl_down_sync(FULL, s, 1);
            s += (tg < 3) ? u : 0.f;
            u = __shfl_down_sync(FULL, s, 2);
            s += (tg < 2) ? u : 0.f;
            sarr[i][nt] = s;
            ft[i][nt] = __shfl_sync(FULL, s, (threadIdx.x & 31) & ~3);
        }
    }

    if (tg == 0) {
        #pragma unroll
        for (int i = 0; i < 4; ++i)
            totbuf[cw * 128 + rown[i]] = ft[i][0] + ft[i][1] + ft[i][2] + ft[i][3];
    }
    cp_wait_all();
    __syncthreads();        // totals + prefetched K/y visible, ONE barrier

    float2 yp[4];
    #pragma unroll
    for (int nt = 0; nt < 4; nt++)
        yp[nt] = *(const float2*)&yblk[cb + nt * 8 + 2 * tg];

    #pragma unroll
    for (int i = 0; i < 4; ++i) {
        const int r = rown[i];
        const float c0t = totbuf[r],       c1t = totbuf[128 + r],
                    c2t = totbuf[256 + r], c3t = totbuf[384 + r];
        float base = carry[i];
        if (cw == 0)      base += c1t + c2t + c3t;
        else if (cw == 1) base += c2t + c3t;
        else if (cw == 2) base += c3t;
        carry[i] += c0t + c1t + c2t + c3t;

        if (live) {
            const int mt = i >> 1, c0i = (i & 1) * 2;
            float fsuf = 0.f;
            #pragma unroll
            for (int nt = 3; nt >= 0; --nt) {
                const float va = acc[mt][nt][c0i];
                const float vb = acc[mt][nt][c0i + 1];
                const float sa = base + fsuf + sarr[i][nt];
                const float wa = va * ex2f(nl2r[i] * sa);
                const float wb = vb * ex2f(nl2r[i] * (sa - va));
                Sacc[i] += wa + wb;
                Yacc[i] += yp[nt].x * wa + yp[nt].y * wb;
                fsuf += ft[i][nt];
            }
        }
    }
}

// ---- Pass 2: main kernel, exact 8-unit bins, single wave of 144 CTAs ----
__global__ __launch_bounds__(NT, 1)
void ema_kernel(const float* __restrict__ y, float* __restrict__ out)
{
    extern __shared__ char smem[];
    __half* q_h  = (__half*)(smem + SM_Q);
    __half* k_h0 = (__half*)(smem + SM_K0);
    __half* k_h1 = (__half*)(smem + SM_K1);
    float*  y2   = (float*)(smem + SM_Y);
    float*  tot  = (float*)(smem + SM_TOT);

    const uint32_t q_sa = (uint32_t)__cvta_generic_to_shared(q_h);
    const uint32_t k_sa[2] = { (uint32_t)__cvta_generic_to_shared(k_h0),
                               (uint32_t)__cvta_generic_to_shared(k_h1) };
    const uint32_t y_sa = (uint32_t)__cvta_generic_to_shared(y2);

    const int tid  = threadIdx.x;
    const int lane = tid & 31;
    const int wid  = tid >> 5;
    const unsigned FULL = 0xffffffffu;

    const int g  = lane >> 2;
    const int tg = lane & 3;
    const int tgbase = tg * 32 + (tg >> 1) * 8;
    const int mrow0 = (wid >> 2) * 32;
    const int cw    = wid & 3;
    const int cb    = cw * 32;

    // job table: every CTA gets exactly 8 work units
    const int bid = blockIdx.x;
    int jb[2], jq[2], njobs;
    if (bid < 32)       { jb[0] = bid;            jq[0] = 7; njobs = 1; }
    else if (bid < 64)  { jb[0] = bid - 32;  jq[0] = 6; jb[1] = jb[0]; jq[1] = 0; njobs = 2; }
    else if (bid < 96)  { jb[0] = bid - 64;  jq[0] = 5; jb[1] = jb[0]; jq[1] = 1; njobs = 2; }
    else if (bid < 128) { jb[0] = bid - 96;  jq[0] = 4; jb[1] = jb[0]; jq[1] = 2; njobs = 2; }
    else { jb[0] = 2 * (bid - 128); jq[0] = 3; jb[1] = jb[0] + 1; jq[1] = 3; njobs = 2; }

    int rown[4];
    #pragma unroll
    for (int i = 0; i < 4; ++i) rown[i] = mrow0 + 8 * i + g;

    // PDL: wait for prep kernel's g_xn / g_nl2 before reading them.
    // (No-op when launched without a programmatic dependency.)
#if __CUDA_ARCH__ >= 900
    cudaGridDependencySynchronize();
#endif

    for (int j = 0; j < njobs; ++j) {
        const int batch = jb[j];
        const int qi    = jq[j];
        const int t0    = qi * 128;

        const __half* xbase = g_xn + (size_t)batch * TLEN * LD_H;
        const float*  ybase = y + batch * TLEN;

        __syncthreads();    // previous job fully done with smem

        // prologue: Q tile (linear 2304 chunks) + y(qi)
        {
            const char* qsrc = (const char*)(xbase + (size_t)t0 * LD_H);
            #pragma unroll
            for (int i = 0; i < 4; ++i) {
                const int c = tid + i * 512;
                cg16(q_sa + c * 16, qsrc + c * 16);
            }
            if (tid < 256) {
                const int c = tid + 2048;
                cg16(q_sa + c * 16, qsrc + c * 16);
            }
            if (tid < 32) cp16(y_sa + tid * 16, ybase + qi * 128 + tid * 4);
        }
        float nl2r[4];
        #pragma unroll
        for (int i = 0; i < 4; ++i)
            nl2r[i] = g_nl2[batch * TLEN + t0 + rown[i]];
        cp_wait_all();
        __syncthreads();

        float carry[4] = {0.f, 0.f, 0.f, 0.f};
        float Sacc[4]  = {0.f, 0.f, 0.f, 0.f};
        float Yacc[4]  = {0.f, 0.f, 0.f, 0.f};

        for (int it = 0; it <= qi; ++it) {
            const int kb = qi - it;

            // prefetch K(kb-1) -> kbuf[it&1], y(kb-1) -> ybuf[(it+1)&1]
            if (kb > 0) {
                const char* ksrc = (const char*)(xbase + (size_t)(kb - 1) * 128 * LD_H);
                const uint32_t dst = k_sa[it & 1];
                #pragma unroll
                for (int i = 0; i < 4; ++i) {
                    const int c = tid + i * 512;
                    cg16(dst + c * 16, ksrc + c * 16);
                }
                if (tid < 256) {
                    const int c = tid + 2048;
                    cg16(dst + c * 16, ksrc + c * 16);
                }
                if (tid < 32)
                    cp16(y_sa + ((it + 1) & 1) * 512 + tid * 16,
                         ybase + (kb - 1) * 128 + tid * 4);
            }

            float* totbuf = tot + (it & 1) * 512;
            const float* yblk = y2 + (it & 1) * 128;
            if (it == 0) {
                process_block<true>(q_h, q_h, yblk, totbuf, nl2r, rown,
                                    carry, Sacc, Yacc, mrow0, cb, cw, g, tg, tgbase);
            } else {
                const __half* bsrc = (it & 1) ? k_h0 : k_h1;   // written at it-1
                process_block<false>(q_h, bsrc, yblk, totbuf, nl2r, rown,
                                     carry, Sacc, Yacc, mrow0, cb, cw, g, tg, tgbase);
            }
        }

        // ---- epilogue ----
        __syncthreads();   // weight loops done reading tot
        #pragma unroll
        for (int i = 0; i < 4; ++i) {
            float s = Sacc[i], yv = Yacc[i];
            s  += __shfl_xor_sync(FULL, s, 1);  s  += __shfl_xor_sync(FULL, s, 2);
            yv += __shfl_xor_sync(FULL, yv, 1); yv += __shfl_xor_sync(FULL, yv, 2);
            if (tg == 0) {
                tot[cw * 128 + rown[i]]       = s;
                tot[512 + cw * 128 + rown[i]] = yv;
            }
        }
        __syncthreads();
        if (cw == 0) {
            #pragma unroll
            for (int i = 0; i < 4; ++i) {
                const int r = rown[i];
                float S = tot[r] + tot[128 + r] + tot[256 + r] + tot[384 + r];
                float Y = tot[512 + r] + tot[640 + r] + tot[768 + r] + tot[896 + r];
                float o = Y / (S + 1e-6f);
                o = fminf(fmaxf(o, 0.01f), 0.99f);
                out[batch * TLEN + t0 + r] = o;
            }
        }
    }
}

extern "C" void kernel_launch(void* const* d_in, const int* in_sizes, int n_in,
                              void* d_out, int out_size)
{
    const float* y    = (const float*)d_in[0];
    const int*   seq  = (const int*)  d_in[1];
    const float* embd = (const float*)d_in[2];
    const float* lw   = (const float*)d_in[3];
    const float* lb   = (const float*)d_in[4];
    float* out = (float*)d_out;

    cudaFuncSetAttribute(ema_kernel,
                         cudaFuncAttributeMaxDynamicSharedMemorySize, SMEM_BYTES);

    prep_kernel<<<BATCH * TLEN / 16, 256>>>(seq, embd, lw, lb);

    // Launch main with programmatic dependent launch so it overlaps prep's tail.
    cudaLaunchConfig_t cfg = {};
    cfg.gridDim  = dim3(144, 1, 1);
    cfg.blockDim = dim3(NT, 1, 1);
    cfg.dynamicSmemBytes = SMEM_BYTES;
    cfg.stream = 0;
    cudaLaunchAttribute attrs[1];
    attrs[0].id = cudaLaunchAttributeProgrammaticStreamSerialization;
    attrs[0].val.programmaticStreamSerializationAllowed = 1;
    cfg.attrs = attrs;
    cfg.numAttrs = 1;
    cudaError_t err = cudaLaunchKernelEx(&cfg, ema_kernel, y, out);
    if (err != cudaSuccess) {
        // fallback: plain serialized launch
        ema_kernel<<<144, NT, SMEM_BYTES>>>(y, out);
    }
}